// round 10
// baseline (speedup 1.0000x reference)
#include <cuda_runtime.h>
#include <math.h>

#define SEQ 2048
#define BATCH 4
#define HEADS 12
#define DMODEL 768
#define HDIM 64
#define INTER 1152
#define ROWS (BATCH*SEQ)   // 8192

// ---------------- scratch (device globals; no allocation allowed) -------------
__device__ float g_xn[ROWS*DMODEL];
__device__ float g_qkv[ROWS*3*DMODEL];
__device__ float g_ctx[ROWS*DMODEL];
__device__ float g_h[ROWS*DMODEL];
__device__ float g_wiout[ROWS*2*INTER];
__device__ float g_glu[ROWS*INTER];

// ---------------- naive two-pass LayerNorm (center=False) ---------------------
__global__ __launch_bounds__(256) void nln_kernel(const float* __restrict__ x,
                                                  const float* __restrict__ gamma,
                                                  float* __restrict__ y) {
    __shared__ float red[256];
    int row = blockIdx.x;
    const float* xr = x + (size_t)row * DMODEL;
    float s = 0.f;
    for (int i = threadIdx.x; i < DMODEL; i += 256) s += xr[i];
    red[threadIdx.x] = s; __syncthreads();
    for (int o = 128; o; o >>= 1) {
        if (threadIdx.x < o) red[threadIdx.x] += red[threadIdx.x + o];
        __syncthreads();
    }
    float mu = red[0] * (1.f / DMODEL);
    __syncthreads();
    float s2 = 0.f;
    for (int i = threadIdx.x; i < DMODEL; i += 256) {
        float d = xr[i] - mu; s2 += d * d;
    }
    red[threadIdx.x] = s2; __syncthreads();
    for (int o = 128; o; o >>= 1) {
        if (threadIdx.x < o) red[threadIdx.x] += red[threadIdx.x + o];
        __syncthreads();
    }
    float inv = rsqrtf(red[0] * (1.f / DMODEL) + 1e-5f);
    for (int i = threadIdx.x; i < DMODEL; i += 256)
        y[(size_t)row * DMODEL + i] = (xr[i] - mu) * inv * gamma[i];
}

// ---------------- naive GEMM: one thread per output element -------------------
// C[r,c] = sum_k A[r,k] * B[k,c] (+ res[r,c])
__global__ __launch_bounds__(256) void ngemm_kernel(const float* __restrict__ A,
                                                    const float* __restrict__ B,
                                                    const float* __restrict__ res,
                                                    float* __restrict__ C,
                                                    int M, int N, int K) {
    int c = blockIdx.x * 32 + threadIdx.x;
    int r = blockIdx.y * 8  + threadIdx.y;
    if (c >= N || r >= M) return;
    const float* a = A + (size_t)r * K;
    float acc = 0.f;
    for (int k = 0; k < K; k++)
        acc += a[k] * B[(size_t)k * N + c];
    if (res) acc += res[(size_t)r * N + c];
    C[(size_t)r * N + c] = acc;
}

// ---------------- naive RoPE: one thread per (row, head, pair) ----------------
__global__ __launch_bounds__(256) void nrope_kernel(float* __restrict__ qkv) {
    int idx = blockIdx.x * 256 + threadIdx.x;
    if (idx >= ROWS * HEADS * 32) return;
    int p = idx & 31;
    int h = (idx >> 5) % HEADS;
    int row = idx / (32 * HEADS);
    int s = row % SEQ;
    // inv_freq = 10000^(-p/32); phase in double for accuracy
    double invf = exp(-(double)p * (9.210340371976184 / 32.0));
    double fr = (double)s * invf;
    float c = (float)cos(fr), sn = (float)sin(fr);
    float* qp = qkv + (size_t)row * (3 * DMODEL) + h * HDIM;
    float a = qp[p], b = qp[p + 32];
    qp[p]      = a * c - b * sn;
    qp[p + 32] = b * c + a * sn;
    float* kp = qp + DMODEL;
    a = kp[p]; b = kp[p + 32];
    kp[p]      = a * c - b * sn;
    kp[p + 32] = b * c + a * sn;
}

// ---------------- naive windowed attention: one block per (b,h,q) row ---------
__global__ __launch_bounds__(128) void nattn_kernel(const float* __restrict__ qkv,
                                                    const float* __restrict__ amask,
                                                    float* __restrict__ ctx) {
    __shared__ float qs[HDIM];
    __shared__ float sc[129];
    __shared__ float red[128];
    int q  = blockIdx.x;
    int bh = blockIdx.y;
    int b = bh / HEADS, h = bh % HEADS;
    int t = threadIdx.x;
    const float* base = qkv + (size_t)(b * SEQ) * (3 * DMODEL) + h * HDIM;
    const float* qrow = base + (size_t)q * (3 * DMODEL);
    if (t < HDIM) qs[t] = qrow[t];
    __syncthreads();

    int lo = q - 64; if (lo < 0) lo = 0;
    int hi = q + 64; if (hi > SEQ - 1) hi = SEQ - 1;
    int nk = hi - lo + 1;   // <= 129

    // scores over valid window (masked keys contribute exp(..)=0 exactly)
    for (int j = t; j < nk; j += 128) {
        const float* krow = base + DMODEL + (size_t)(lo + j) * (3 * DMODEL);
        float acc = 0.f;
        for (int d = 0; d < HDIM; d++) acc += qs[d] * krow[d];
        sc[j] = acc * 0.125f + amask[(size_t)(b * SEQ + q) * SEQ + lo + j];
    }
    __syncthreads();

    // max reduce
    float m = -3.4e38f;
    for (int j = t; j < nk; j += 128) m = fmaxf(m, sc[j]);
    red[t] = m; __syncthreads();
    for (int o = 64; o; o >>= 1) {
        if (t < o) red[t] = fmaxf(red[t], red[t + o]);
        __syncthreads();
    }
    m = red[0];
    __syncthreads();

    // exp + sum reduce
    float s = 0.f;
    for (int j = t; j < nk; j += 128) {
        float p = expf(sc[j] - m);
        sc[j] = p;
        s += p;
    }
    red[t] = s; __syncthreads();
    for (int o = 64; o; o >>= 1) {
        if (t < o) red[t] += red[t + o];
        __syncthreads();
    }
    float inv = 1.f / red[0];

    // ctx: threads 0..63 each handle one output dim
    if (t < HDIM) {
        const float* vbase = base + 2 * DMODEL;
        float acc = 0.f;
        for (int j = 0; j < nk; j++)
            acc += sc[j] * vbase[(size_t)(lo + j) * (3 * DMODEL) + t];
        ctx[(size_t)(b * SEQ + q) * DMODEL + h * HDIM + t] = acc * inv;
    }
}

// ---------------- naive GLU: gelu(x) * gate ------------------------------------
__global__ __launch_bounds__(256) void nglu_kernel(const float* __restrict__ wiout,
                                                   float* __restrict__ glu) {
    size_t idx = (size_t)blockIdx.x * 256 + threadIdx.x;
    if (idx >= (size_t)ROWS * INTER) return;
    size_t row = idx / INTER;
    int col = (int)(idx % INTER);
    float x    = wiout[row * (2 * INTER) + col];
    float gate = wiout[row * (2 * INTER) + col + INTER];
    float ge = 0.5f * x * (1.f + erff(x * 0.70710678118654752f));
    glu[idx] = ge * gate;
}

// ------------------------------------------------------------------------------
extern "C" void kernel_launch(void* const* d_in, const int* in_sizes, int n_in,
                              void* d_out, int out_size) {
    const float* hidden  = (const float*)d_in[0];
    const float* amask   = (const float*)d_in[1];
    const float* g1      = (const float*)d_in[2];
    const float* wqkv    = (const float*)d_in[3];
    const float* wo_attn = (const float*)d_in[4];
    const float* g2      = (const float*)d_in[5];
    const float* wi      = (const float*)d_in[6];
    const float* wo_mlp  = (const float*)d_in[7];
    float* out = (float*)d_out;

    float *xn, *qkv, *ctx, *h, *wiout, *glu;
    cudaGetSymbolAddress((void**)&xn,    g_xn);
    cudaGetSymbolAddress((void**)&qkv,   g_qkv);
    cudaGetSymbolAddress((void**)&ctx,   g_ctx);
    cudaGetSymbolAddress((void**)&h,     g_h);
    cudaGetSymbolAddress((void**)&wiout, g_wiout);
    cudaGetSymbolAddress((void**)&glu,   g_glu);

    dim3 blk(32, 8);

    // 1. pre-attn LN
    nln_kernel<<<ROWS, 256>>>(hidden, g1, xn);
    // 2. QKV projection: [8192,768] @ [768,2304]
    ngemm_kernel<<<dim3((3*DMODEL)/32, ROWS/8), blk>>>(xn, wqkv, nullptr, qkv,
                                                       ROWS, 3*DMODEL, DMODEL);
    // 3. RoPE
    nrope_kernel<<<(ROWS*HEADS*32)/256, 256>>>(qkv);
    // 4. windowed attention (naive, per-row)
    nattn_kernel<<<dim3(SEQ, BATCH*HEADS), 128>>>(qkv, amask, ctx);
    // 5. output projection + residual
    ngemm_kernel<<<dim3(DMODEL/32, ROWS/8), blk>>>(ctx, wo_attn, hidden, h,
                                                   ROWS, DMODEL, DMODEL);
    // 6. pre-MLP LN
    nln_kernel<<<ROWS, 256>>>(h, g2, xn);
    // 7. Wi projection
    ngemm_kernel<<<dim3((2*INTER)/32, ROWS/8), blk>>>(xn, wi, nullptr, wiout,
                                                      ROWS, 2*INTER, DMODEL);
    // 8. GLU
    nglu_kernel<<<((size_t)ROWS*INTER + 255)/256, 256>>>(wiout, glu);
    // 9. Wo projection + residual
    ngemm_kernel<<<dim3(DMODEL/32, ROWS/8), blk>>>(glu, wo_mlp, h, out,
                                                   ROWS, DMODEL, INTER);
}

// round 12
// speedup vs baseline: 2.4173x; 2.4173x over previous
#include <cuda_runtime.h>
#include <math.h>

#define SEQ 2048
#define BATCH 4
#define HEADS 12
#define DMODEL 768
#define HDIM 64
#define INTER 1152
#define ROWS (BATCH*SEQ)   // 8192

// ---------------- scratch (device globals; no allocation allowed) -------------
__device__ float g_xn[ROWS*DMODEL];
__device__ float g_qkv[ROWS*3*DMODEL];
__device__ float g_ctx[ROWS*DMODEL];
__device__ float g_h[ROWS*DMODEL];
__device__ float g_wiout[ROWS*2*INTER];
__device__ float g_glu[ROWS*INTER];

// ---------------- naive two-pass LayerNorm (center=False) — from PASSING R10 --
__global__ __launch_bounds__(256) void nln_kernel(const float* __restrict__ x,
                                                  const float* __restrict__ gamma,
                                                  float* __restrict__ y) {
    __shared__ float red[256];
    int row = blockIdx.x;
    const float* xr = x + (size_t)row * DMODEL;
    float s = 0.f;
    for (int i = threadIdx.x; i < DMODEL; i += 256) s += xr[i];
    red[threadIdx.x] = s; __syncthreads();
    for (int o = 128; o; o >>= 1) {
        if (threadIdx.x < o) red[threadIdx.x] += red[threadIdx.x + o];
        __syncthreads();
    }
    float mu = red[0] * (1.f / DMODEL);
    __syncthreads();
    float s2 = 0.f;
    for (int i = threadIdx.x; i < DMODEL; i += 256) {
        float d = xr[i] - mu; s2 += d * d;
    }
    red[threadIdx.x] = s2; __syncthreads();
    for (int o = 128; o; o >>= 1) {
        if (threadIdx.x < o) red[threadIdx.x] += red[threadIdx.x + o];
        __syncthreads();
    }
    float inv = rsqrtf(red[0] * (1.f / DMODEL) + 1e-5f);
    for (int i = threadIdx.x; i < DMODEL; i += 256)
        y[(size_t)row * DMODEL + i] = (xr[i] - mu) * inv * gamma[i];
}

// ---------------- tiled SGEMM 128x128x16, 8x8 register tile (ONLY change) -----
#define GBM 128
#define GBN 128
#define GBK 16
__global__ __launch_bounds__(256) void sgemm2_kernel(const float* __restrict__ A,
                                                     const float* __restrict__ B,
                                                     const float* __restrict__ res,
                                                     float* __restrict__ C,
                                                     int M, int N, int K) {
    __shared__ float As[GBK][GBM];
    __shared__ float Bs[GBK][GBN];
    int tid = threadIdx.x;
    int tx = tid & 15;        // 16 thread-cols * 8 = 128 N
    int ty = tid >> 4;        // 16 thread-rows * 8 = 128 M
    int m0 = blockIdx.y * GBM;
    int n0 = blockIdx.x * GBN;

    int am = tid >> 2;            // 0..63  (A tile row; +64 for second half)
    int ak = (tid & 3) * 4;       // 0,4,8,12
    int bk = tid >> 5;            // 0..7   (B tile row; +8 for second half)
    int bn = (tid & 31) * 4;      // 0..124

    float acc[8][8] = {};
    for (int k0 = 0; k0 < K; k0 += GBK) {
        float4 a0 = *(const float4*)(A + (size_t)(m0 + am)      * K + k0 + ak);
        float4 a1 = *(const float4*)(A + (size_t)(m0 + am + 64) * K + k0 + ak);
        As[ak+0][am]    = a0.x; As[ak+1][am]    = a0.y;
        As[ak+2][am]    = a0.z; As[ak+3][am]    = a0.w;
        As[ak+0][am+64] = a1.x; As[ak+1][am+64] = a1.y;
        As[ak+2][am+64] = a1.z; As[ak+3][am+64] = a1.w;
        *(float4*)(&Bs[bk][bn])   = *(const float4*)(B + (size_t)(k0 + bk)     * N + n0 + bn);
        *(float4*)(&Bs[bk+8][bn]) = *(const float4*)(B + (size_t)(k0 + bk + 8) * N + n0 + bn);
        __syncthreads();
        #pragma unroll
        for (int k = 0; k < GBK; k++) {
            float ar[8], br[8];
            #pragma unroll
            for (int i = 0; i < 8; i++) ar[i] = As[k][ty*8 + i];
            #pragma unroll
            for (int j = 0; j < 8; j++) br[j] = Bs[k][tx*8 + j];
            #pragma unroll
            for (int i = 0; i < 8; i++)
                #pragma unroll
                for (int j = 0; j < 8; j++) acc[i][j] += ar[i] * br[j];
        }
        __syncthreads();
    }
    #pragma unroll
    for (int i = 0; i < 8; i++) {
        size_t r = m0 + ty*8 + i;
        #pragma unroll
        for (int j = 0; j < 8; j += 4) {
            size_t off = r * N + n0 + tx*8 + j;
            float4 v = make_float4(acc[i][j], acc[i][j+1], acc[i][j+2], acc[i][j+3]);
            if (res) {
                float4 rv = *(const float4*)(res + off);
                v.x += rv.x; v.y += rv.y; v.z += rv.z; v.w += rv.w;
            }
            *(float4*)(C + off) = v;
        }
    }
}

// ---------------- naive RoPE — from PASSING R10, UNCHANGED --------------------
__global__ __launch_bounds__(256) void nrope_kernel(float* __restrict__ qkv) {
    int idx = blockIdx.x * 256 + threadIdx.x;
    if (idx >= ROWS * HEADS * 32) return;
    int p = idx & 31;
    int h = (idx >> 5) % HEADS;
    int row = idx / (32 * HEADS);
    int s = row % SEQ;
    double invf = exp(-(double)p * (9.210340371976184 / 32.0));
    double fr = (double)s * invf;
    float c = (float)cos(fr), sn = (float)sin(fr);
    float* qp = qkv + (size_t)row * (3 * DMODEL) + h * HDIM;
    float a = qp[p], b = qp[p + 32];
    qp[p]      = a * c - b * sn;
    qp[p + 32] = b * c + a * sn;
    float* kp = qp + DMODEL;
    a = kp[p]; b = kp[p + 32];
    kp[p]      = a * c - b * sn;
    kp[p + 32] = b * c + a * sn;
}

// ---------------- naive windowed attention — from PASSING R10, UNCHANGED ------
__global__ __launch_bounds__(128) void nattn_kernel(const float* __restrict__ qkv,
                                                    const float* __restrict__ amask,
                                                    float* __restrict__ ctx) {
    __shared__ float qs[HDIM];
    __shared__ float sc[129];
    __shared__ float red[128];
    int q  = blockIdx.x;
    int bh = blockIdx.y;
    int b = bh / HEADS, h = bh % HEADS;
    int t = threadIdx.x;
    const float* base = qkv + (size_t)(b * SEQ) * (3 * DMODEL) + h * HDIM;
    const float* qrow = base + (size_t)q * (3 * DMODEL);
    if (t < HDIM) qs[t] = qrow[t];
    __syncthreads();

    int lo = q - 64; if (lo < 0) lo = 0;
    int hi = q + 64; if (hi > SEQ - 1) hi = SEQ - 1;
    int nk = hi - lo + 1;   // <= 129

    for (int j = t; j < nk; j += 128) {
        const float* krow = base + DMODEL + (size_t)(lo + j) * (3 * DMODEL);
        float acc = 0.f;
        for (int d = 0; d < HDIM; d++) acc += qs[d] * krow[d];
        sc[j] = acc * 0.125f + amask[(size_t)(b * SEQ + q) * SEQ + lo + j];
    }
    __syncthreads();

    float m = -3.4e38f;
    for (int j = t; j < nk; j += 128) m = fmaxf(m, sc[j]);
    red[t] = m; __syncthreads();
    for (int o = 64; o; o >>= 1) {
        if (t < o) red[t] = fmaxf(red[t], red[t + o]);
        __syncthreads();
    }
    m = red[0];
    __syncthreads();

    float s = 0.f;
    for (int j = t; j < nk; j += 128) {
        float p = expf(sc[j] - m);
        sc[j] = p;
        s += p;
    }
    red[t] = s; __syncthreads();
    for (int o = 64; o; o >>= 1) {
        if (t < o) red[t] += red[t + o];
        __syncthreads();
    }
    float inv = 1.f / red[0];

    if (t < HDIM) {
        const float* vbase = base + 2 * DMODEL;
        float acc = 0.f;
        for (int j = 0; j < nk; j++)
            acc += sc[j] * vbase[(size_t)(lo + j) * (3 * DMODEL) + t];
        ctx[(size_t)(b * SEQ + q) * DMODEL + h * HDIM + t] = acc * inv;
    }
}

// ---------------- naive GLU — from PASSING R10, UNCHANGED ---------------------
__global__ __launch_bounds__(256) void nglu_kernel(const float* __restrict__ wiout,
                                                   float* __restrict__ glu) {
    size_t idx = (size_t)blockIdx.x * 256 + threadIdx.x;
    if (idx >= (size_t)ROWS * INTER) return;
    size_t row = idx / INTER;
    int col = (int)(idx % INTER);
    float x    = wiout[row * (2 * INTER) + col];
    float gate = wiout[row * (2 * INTER) + col + INTER];
    float ge = 0.5f * x * (1.f + erff(x * 0.70710678118654752f));
    glu[idx] = ge * gate;
}

// ------------------------------------------------------------------------------
extern "C" void kernel_launch(void* const* d_in, const int* in_sizes, int n_in,
                              void* d_out, int out_size) {
    const float* hidden  = (const float*)d_in[0];
    const float* amask   = (const float*)d_in[1];
    const float* g1      = (const float*)d_in[2];
    const float* wqkv    = (const float*)d_in[3];
    const float* wo_attn = (const float*)d_in[4];
    const float* g2      = (const float*)d_in[5];
    const float* wi      = (const float*)d_in[6];
    const float* wo_mlp  = (const float*)d_in[7];
    float* out = (float*)d_out;

    float *xn, *qkv, *ctx, *h, *wiout, *glu;
    cudaGetSymbolAddress((void**)&xn,    g_xn);
    cudaGetSymbolAddress((void**)&qkv,   g_qkv);
    cudaGetSymbolAddress((void**)&ctx,   g_ctx);
    cudaGetSymbolAddress((void**)&h,     g_h);
    cudaGetSymbolAddress((void**)&wiout, g_wiout);
    cudaGetSymbolAddress((void**)&glu,   g_glu);

    // 1. pre-attn LN
    nln_kernel<<<ROWS, 256>>>(hidden, g1, xn);
    // 2. QKV projection: [8192,768] @ [768,2304]
    sgemm2_kernel<<<dim3((3*DMODEL)/GBN, ROWS/GBM), 256>>>(xn, wqkv, nullptr, qkv,
                                                           ROWS, 3*DMODEL, DMODEL);
    // 3. RoPE (naive, passing version)
    nrope_kernel<<<(ROWS*HEADS*32)/256, 256>>>(qkv);
    // 4. windowed attention (naive, passing version)
    nattn_kernel<<<dim3(SEQ, BATCH*HEADS), 128>>>(qkv, amask, ctx);
    // 5. output projection + residual
    sgemm2_kernel<<<dim3(DMODEL/GBN, ROWS/GBM), 256>>>(ctx, wo_attn, hidden, h,
                                                       ROWS, DMODEL, DMODEL);
    // 6. pre-MLP LN
    nln_kernel<<<ROWS, 256>>>(h, g2, xn);
    // 7. Wi projection
    sgemm2_kernel<<<dim3((2*INTER)/GBN, ROWS/GBM), 256>>>(xn, wi, nullptr, wiout,
                                                          ROWS, 2*INTER, DMODEL);
    // 8. GLU
    nglu_kernel<<<((size_t)ROWS*INTER + 255)/256, 256>>>(wiout, glu);
    // 9. Wo projection + residual
    sgemm2_kernel<<<dim3(DMODEL/GBN, ROWS/GBM), 256>>>(glu, wo_mlp, h, out,
                                                       ROWS, DMODEL, INTER);
}

// round 14
// speedup vs baseline: 5.0072x; 2.0714x over previous
#include <cuda_runtime.h>
#include <cuda_bf16.h>
#include <math.h>

#define SEQ 2048
#define BATCH 4
#define HEADS 12
#define DMODEL 768
#define HDIM 64
#define INTER 1152
#define ROWS (BATCH*SEQ)   // 8192

// ---------------- scratch (device globals; no allocation allowed) -------------
__device__ float g_xn[ROWS*DMODEL];
__device__ float g_qkv[ROWS*3*DMODEL];
__device__ float g_ctx[ROWS*DMODEL];
__device__ float g_h[ROWS*DMODEL];
__device__ float g_wiout[ROWS*2*INTER];
__device__ float g_glu[ROWS*INTER];

// ---------------- naive two-pass LayerNorm — from PASSING R12, UNCHANGED ------
__global__ __launch_bounds__(256) void nln_kernel(const float* __restrict__ x,
                                                  const float* __restrict__ gamma,
                                                  float* __restrict__ y) {
    __shared__ float red[256];
    int row = blockIdx.x;
    const float* xr = x + (size_t)row * DMODEL;
    float s = 0.f;
    for (int i = threadIdx.x; i < DMODEL; i += 256) s += xr[i];
    red[threadIdx.x] = s; __syncthreads();
    for (int o = 128; o; o >>= 1) {
        if (threadIdx.x < o) red[threadIdx.x] += red[threadIdx.x + o];
        __syncthreads();
    }
    float mu = red[0] * (1.f / DMODEL);
    __syncthreads();
    float s2 = 0.f;
    for (int i = threadIdx.x; i < DMODEL; i += 256) {
        float d = xr[i] - mu; s2 += d * d;
    }
    red[threadIdx.x] = s2; __syncthreads();
    for (int o = 128; o; o >>= 1) {
        if (threadIdx.x < o) red[threadIdx.x] += red[threadIdx.x + o];
        __syncthreads();
    }
    float inv = rsqrtf(red[0] * (1.f / DMODEL) + 1e-5f);
    for (int i = threadIdx.x; i < DMODEL; i += 256)
        y[(size_t)row * DMODEL + i] = (xr[i] - mu) * inv * gamma[i];
}

// ---------------- tiled SGEMM 128x128x16 — from PASSING R12, UNCHANGED --------
#define GBM 128
#define GBN 128
#define GBK 16
__global__ __launch_bounds__(256) void sgemm2_kernel(const float* __restrict__ A,
                                                     const float* __restrict__ B,
                                                     const float* __restrict__ res,
                                                     float* __restrict__ C,
                                                     int M, int N, int K) {
    __shared__ float As[GBK][GBM];
    __shared__ float Bs[GBK][GBN];
    int tid = threadIdx.x;
    int tx = tid & 15;
    int ty = tid >> 4;
    int m0 = blockIdx.y * GBM;
    int n0 = blockIdx.x * GBN;

    int am = tid >> 2;
    int ak = (tid & 3) * 4;
    int bk = tid >> 5;
    int bn = (tid & 31) * 4;

    float acc[8][8] = {};
    for (int k0 = 0; k0 < K; k0 += GBK) {
        float4 a0 = *(const float4*)(A + (size_t)(m0 + am)      * K + k0 + ak);
        float4 a1 = *(const float4*)(A + (size_t)(m0 + am + 64) * K + k0 + ak);
        As[ak+0][am]    = a0.x; As[ak+1][am]    = a0.y;
        As[ak+2][am]    = a0.z; As[ak+3][am]    = a0.w;
        As[ak+0][am+64] = a1.x; As[ak+1][am+64] = a1.y;
        As[ak+2][am+64] = a1.z; As[ak+3][am+64] = a1.w;
        *(float4*)(&Bs[bk][bn])   = *(const float4*)(B + (size_t)(k0 + bk)     * N + n0 + bn);
        *(float4*)(&Bs[bk+8][bn]) = *(const float4*)(B + (size_t)(k0 + bk + 8) * N + n0 + bn);
        __syncthreads();
        #pragma unroll
        for (int k = 0; k < GBK; k++) {
            float ar[8], br[8];
            #pragma unroll
            for (int i = 0; i < 8; i++) ar[i] = As[k][ty*8 + i];
            #pragma unroll
            for (int j = 0; j < 8; j++) br[j] = Bs[k][tx*8 + j];
            #pragma unroll
            for (int i = 0; i < 8; i++)
                #pragma unroll
                for (int j = 0; j < 8; j++) acc[i][j] += ar[i] * br[j];
        }
        __syncthreads();
    }
    #pragma unroll
    for (int i = 0; i < 8; i++) {
        size_t r = m0 + ty*8 + i;
        #pragma unroll
        for (int j = 0; j < 8; j += 4) {
            size_t off = r * N + n0 + tx*8 + j;
            float4 v = make_float4(acc[i][j], acc[i][j+1], acc[i][j+2], acc[i][j+3]);
            if (res) {
                float4 rv = *(const float4*)(res + off);
                v.x += rv.x; v.y += rv.y; v.z += rv.z; v.w += rv.w;
            }
            *(float4*)(C + off) = v;
        }
    }
}

// ---------------- naive RoPE — from PASSING R12, UNCHANGED --------------------
__global__ __launch_bounds__(256) void nrope_kernel(float* __restrict__ qkv) {
    int idx = blockIdx.x * 256 + threadIdx.x;
    if (idx >= ROWS * HEADS * 32) return;
    int p = idx & 31;
    int h = (idx >> 5) % HEADS;
    int row = idx / (32 * HEADS);
    int s = row % SEQ;
    double invf = exp(-(double)p * (9.210340371976184 / 32.0));
    double fr = (double)s * invf;
    float c = (float)cos(fr), sn = (float)sin(fr);
    float* qp = qkv + (size_t)row * (3 * DMODEL) + h * HDIM;
    float a = qp[p], b = qp[p + 32];
    qp[p]      = a * c - b * sn;
    qp[p + 32] = b * c + a * sn;
    float* kp = qp + DMODEL;
    a = kp[p]; b = kp[p + 32];
    kp[p]      = a * c - b * sn;
    kp[p + 32] = b * c + a * sn;
}

// ---------------- flash-style windowed attention (static smem <48KB) ----------
// Block = (32-query tile, b*H), 256 threads = 8 warps; warp w owns q rows
// qtile*32 + w*4 .. +3 sequentially. K/V window (160 rows) staged in bf16.
// NO dynamic smem, NO cudaFuncSetAttribute — static total = 44288 B.
__global__ __launch_bounds__(256) void fattn_kernel(const float* __restrict__ qkv,
                                                    const float* __restrict__ amask,
                                                    float* __restrict__ ctx) {
    __shared__ __nv_bfloat162 Ks[160][33];   // 64 dims as 32 pairs + 1 pad
    __shared__ __nv_bfloat162 Vs[160][33];
    __shared__ float Qw[8][64];              // per-warp current Q row (fp32)

    int q0 = blockIdx.x * 32;
    int bh = blockIdx.y;
    int b = bh / HEADS, h = bh % HEADS;
    int t = threadIdx.x, w = t >> 5, lane = t & 31;
    const float* base  = qkv + (size_t)(b * SEQ) * (3*DMODEL) + h * HDIM;
    const float* kbase = base + DMODEL;
    const float* vbase = base + 2*DMODEL;

    // stage K,V window rows [q0-64, q0+96) as bf16 (invalid rows never read)
    for (int i = t; i < 160 * 32; i += 256) {
        int row = i >> 5, pr = i & 31;
        int kg = q0 - 64 + row;
        if (kg >= 0 && kg < SEQ) {
            size_t off = (size_t)kg * (3*DMODEL) + 2*pr;
            float2 kv = *(const float2*)(kbase + off);
            Ks[row][pr] = __floats2bfloat162_rn(kv.x, kv.y);
            float2 vv = *(const float2*)(vbase + off);
            Vs[row][pr] = __floats2bfloat162_rn(vv.x, vv.y);
        }
    }
    __syncthreads();

    for (int r = 0; r < 4; r++) {
        int qi = w * 4 + r;
        int q  = q0 + qi;
        // load this row's Q (fp32) into the warp's strip
        const float* qrow = base + (size_t)q * (3*DMODEL);
        Qw[w][lane]      = qrow[lane];
        Qw[w][lane + 32] = qrow[lane + 32];
        __syncwarp();

        int lo = q - 64; if (lo < 0) lo = 0;
        int hi = q + 64; if (hi > SEQ - 1) hi = SEQ - 1;
        const float* mrow = amask + (size_t)(b * SEQ + q) * SEQ;

        // scores: lane covers keys lo+lane+32c, c=0..4 (register-resident)
        float pc[5];
        float m = -1e30f;
        #pragma unroll
        for (int c = 0; c < 5; c++) {
            int j = lo + lane + 32*c;
            float sc = -1e30f;
            if (j <= hi) {
                int jl = j - (q0 - 64);
                float acc = 0.f;
                #pragma unroll
                for (int dp = 0; dp < 32; dp++) {
                    __nv_bfloat162 kk = Ks[jl][dp];
                    acc += Qw[w][2*dp]   * __bfloat162float(kk.x)
                         + Qw[w][2*dp+1] * __bfloat162float(kk.y);
                }
                sc = acc * 0.125f + mrow[j];
            }
            pc[c] = sc;
            m = fmaxf(m, sc);
        }
        #pragma unroll
        for (int o = 16; o; o >>= 1) m = fmaxf(m, __shfl_xor_sync(0xffffffffu, m, o));

        float s = 0.f;
        #pragma unroll
        for (int c = 0; c < 5; c++) {
            pc[c] = expf(pc[c] - m);   // invalid lanes: exp(-huge)=0
            s += pc[c];
        }
        #pragma unroll
        for (int o = 16; o; o >>= 1) s += __shfl_xor_sync(0xffffffffu, s, o);
        float inv = 1.f / s;

        // P@V: lane accumulates output dims {2*lane, 2*lane+1}
        float a0 = 0.f, a1 = 0.f;
        #pragma unroll
        for (int c = 0; c < 5; c++) {
            int jbase = lo + 32*c;
            if (jbase > hi) break;
            int jmax = hi - jbase; if (jmax > 31) jmax = 31;
            int jl0 = jbase - (q0 - 64);
            for (int jj = 0; jj <= jmax; jj++) {
                float p = __shfl_sync(0xffffffffu, pc[c], jj);
                __nv_bfloat162 v = Vs[jl0 + jj][lane];
                a0 += p * __bfloat162float(v.x);
                a1 += p * __bfloat162float(v.y);
            }
        }
        float* o = ctx + (size_t)(b * SEQ + q) * DMODEL + h * HDIM + 2*lane;
        o[0] = a0 * inv;
        o[1] = a1 * inv;
        __syncwarp();
    }
}

// ---------------- naive GLU — from PASSING R12, UNCHANGED ---------------------
__global__ __launch_bounds__(256) void nglu_kernel(const float* __restrict__ wiout,
                                                   float* __restrict__ glu) {
    size_t idx = (size_t)blockIdx.x * 256 + threadIdx.x;
    if (idx >= (size_t)ROWS * INTER) return;
    size_t row = idx / INTER;
    int col = (int)(idx % INTER);
    float x    = wiout[row * (2 * INTER) + col];
    float gate = wiout[row * (2 * INTER) + col + INTER];
    float ge = 0.5f * x * (1.f + erff(x * 0.70710678118654752f));
    glu[idx] = ge * gate;
}

// ------------------------------------------------------------------------------
extern "C" void kernel_launch(void* const* d_in, const int* in_sizes, int n_in,
                              void* d_out, int out_size) {
    const float* hidden  = (const float*)d_in[0];
    const float* amask   = (const float*)d_in[1];
    const float* g1      = (const float*)d_in[2];
    const float* wqkv    = (const float*)d_in[3];
    const float* wo_attn = (const float*)d_in[4];
    const float* g2      = (const float*)d_in[5];
    const float* wi      = (const float*)d_in[6];
    const float* wo_mlp  = (const float*)d_in[7];
    float* out = (float*)d_out;

    float *xn, *qkv, *ctx, *h, *wiout, *glu;
    cudaGetSymbolAddress((void**)&xn,    g_xn);
    cudaGetSymbolAddress((void**)&qkv,   g_qkv);
    cudaGetSymbolAddress((void**)&ctx,   g_ctx);
    cudaGetSymbolAddress((void**)&h,     g_h);
    cudaGetSymbolAddress((void**)&wiout, g_wiout);
    cudaGetSymbolAddress((void**)&glu,   g_glu);

    // 1. pre-attn LN
    nln_kernel<<<ROWS, 256>>>(hidden, g1, xn);
    // 2. QKV projection: [8192,768] @ [768,2304]
    sgemm2_kernel<<<dim3((3*DMODEL)/GBN, ROWS/GBM), 256>>>(xn, wqkv, nullptr, qkv,
                                                           ROWS, 3*DMODEL, DMODEL);
    // 3. RoPE (naive, passing version)
    nrope_kernel<<<(ROWS*HEADS*32)/256, 256>>>(qkv);
    // 4. windowed attention (static-smem flash-style)
    fattn_kernel<<<dim3(SEQ/32, BATCH*HEADS), 256>>>(qkv, amask, ctx);
    // 5. output projection + residual
    sgemm2_kernel<<<dim3(DMODEL/GBN, ROWS/GBM), 256>>>(ctx, wo_attn, hidden, h,
                                                       ROWS, DMODEL, DMODEL);
    // 6. pre-MLP LN
    nln_kernel<<<ROWS, 256>>>(h, g2, xn);
    // 7. Wi projection
    sgemm2_kernel<<<dim3((2*INTER)/GBN, ROWS/GBM), 256>>>(xn, wi, nullptr, wiout,
                                                          ROWS, 2*INTER, DMODEL);
    // 8. GLU
    nglu_kernel<<<((size_t)ROWS*INTER + 255)/256, 256>>>(wiout, glu);
    // 9. Wo projection + residual
    sgemm2_kernel<<<dim3(DMODEL/GBN, ROWS/GBM), 256>>>(glu, wo_mlp, h, out,
                                                       ROWS, DMODEL, INTER);
}

// round 16
// speedup vs baseline: 9.4016x; 1.8776x over previous
#include <cuda_runtime.h>
#include <cuda_bf16.h>
#include <math.h>

#define SEQ 2048
#define BATCH 4
#define HEADS 12
#define DMODEL 768
#define HDIM 64
#define INTER 1152
#define ROWS (BATCH*SEQ)   // 8192

// ---------------- scratch (device globals; no allocation allowed) -------------
__device__ float g_xn[ROWS*DMODEL];
__device__ float g_qkv[ROWS*3*DMODEL];
__device__ float g_ctx[ROWS*DMODEL];
__device__ float g_h[ROWS*DMODEL];
__device__ float g_wiout[ROWS*2*INTER];
__device__ float g_glu[ROWS*INTER];

// ---------------- naive two-pass LayerNorm — UNCHANGED (passing R14) ----------
__global__ __launch_bounds__(256) void nln_kernel(const float* __restrict__ x,
                                                  const float* __restrict__ gamma,
                                                  float* __restrict__ y) {
    __shared__ float red[256];
    int row = blockIdx.x;
    const float* xr = x + (size_t)row * DMODEL;
    float s = 0.f;
    for (int i = threadIdx.x; i < DMODEL; i += 256) s += xr[i];
    red[threadIdx.x] = s; __syncthreads();
    for (int o = 128; o; o >>= 1) {
        if (threadIdx.x < o) red[threadIdx.x] += red[threadIdx.x + o];
        __syncthreads();
    }
    float mu = red[0] * (1.f / DMODEL);
    __syncthreads();
    float s2 = 0.f;
    for (int i = threadIdx.x; i < DMODEL; i += 256) {
        float d = xr[i] - mu; s2 += d * d;
    }
    red[threadIdx.x] = s2; __syncthreads();
    for (int o = 128; o; o >>= 1) {
        if (threadIdx.x < o) red[threadIdx.x] += red[threadIdx.x + o];
        __syncthreads();
    }
    float inv = rsqrtf(red[0] * (1.f / DMODEL) + 1e-5f);
    for (int i = threadIdx.x; i < DMODEL; i += 256)
        y[(size_t)row * DMODEL + i] = (xr[i] - mu) * inv * gamma[i];
}

// ---------------- tf32 tensor-core GEMM (mma.sync.m16n8k8) --------------------
// Block 128x128x32, 256 threads = 8 warps (2M x 4N), warp tile 64x32.
// Smem: As[k][m] (A transposed), Bs[k][n], both tf32, ld=136. Static smem
// 34816 B. C = A@B (+res), fp32 accumulate.
#define TBM 128
#define TBN 128
#define TBK 32
#define TLD 136

__device__ __forceinline__ unsigned f2tf(float f) {
    unsigned u;
    asm("cvt.rna.tf32.f32 %0, %1;" : "=r"(u) : "f"(f));
    return u;
}

__global__ __launch_bounds__(256) void tgemm_kernel(const float* __restrict__ A,
                                                    const float* __restrict__ B,
                                                    const float* __restrict__ res,
                                                    float* __restrict__ C,
                                                    int M, int N, int K) {
    __shared__ unsigned As[TBK][TLD];
    __shared__ unsigned Bs[TBK][TLD];
    int tid = threadIdx.x;
    int lane = tid & 31, wid = tid >> 5;
    int warpM = wid >> 2;          // 0..1 -> 64 rows each
    int warpN = wid & 3;           // 0..3 -> 32 cols each
    int gid = lane >> 2, tig = lane & 3;
    int m0 = blockIdx.y * TBM, n0 = blockIdx.x * TBN;

    float c[4][4][4] = {};

    int arow = tid >> 1;           // 0..127
    int akc  = (tid & 1) * 16;     // 0 or 16
    int bk   = tid >> 3;           // 0..31
    int bc   = tid & 7;            // 8 threads per B row

    for (int k0 = 0; k0 < K; k0 += TBK) {
        const float* ag = A + (size_t)(m0 + arow) * K + k0 + akc;
        #pragma unroll
        for (int i = 0; i < 4; i++) {
            float4 av = *(const float4*)(ag + i * 4);
            As[akc + i*4 + 0][arow] = f2tf(av.x);
            As[akc + i*4 + 1][arow] = f2tf(av.y);
            As[akc + i*4 + 2][arow] = f2tf(av.z);
            As[akc + i*4 + 3][arow] = f2tf(av.w);
        }
        const float* bg = B + (size_t)(k0 + bk) * N + n0;
        #pragma unroll
        for (int j = 0; j < 4; j++) {
            int colf = (bc + 8*j) * 4;
            float4 bv = *(const float4*)(bg + colf);
            Bs[bk][colf + 0] = f2tf(bv.x);
            Bs[bk][colf + 1] = f2tf(bv.y);
            Bs[bk][colf + 2] = f2tf(bv.z);
            Bs[bk][colf + 3] = f2tf(bv.w);
        }
        __syncthreads();

        #pragma unroll
        for (int ks = 0; ks < TBK; ks += 8) {
            unsigned a[4][4], b[4][2];
            #pragma unroll
            for (int mt = 0; mt < 4; mt++) {
                int mb = warpM * 64 + mt * 16;
                a[mt][0] = As[ks + tig]    [mb + gid];
                a[mt][1] = As[ks + tig]    [mb + gid + 8];
                a[mt][2] = As[ks + tig + 4][mb + gid];
                a[mt][3] = As[ks + tig + 4][mb + gid + 8];
            }
            #pragma unroll
            for (int nt = 0; nt < 4; nt++) {
                int nb = warpN * 32 + nt * 8;
                b[nt][0] = Bs[ks + tig]    [nb + gid];
                b[nt][1] = Bs[ks + tig + 4][nb + gid];
            }
            #pragma unroll
            for (int mt = 0; mt < 4; mt++)
                #pragma unroll
                for (int nt = 0; nt < 4; nt++) {
                    asm volatile(
                        "mma.sync.aligned.m16n8k8.row.col.f32.tf32.tf32.f32 "
                        "{%0,%1,%2,%3}, {%4,%5,%6,%7}, {%8,%9}, {%0,%1,%2,%3};"
                        : "+f"(c[mt][nt][0]), "+f"(c[mt][nt][1]),
                          "+f"(c[mt][nt][2]), "+f"(c[mt][nt][3])
                        : "r"(a[mt][0]), "r"(a[mt][1]), "r"(a[mt][2]), "r"(a[mt][3]),
                          "r"(b[nt][0]), "r"(b[nt][1]));
                }
        }
        __syncthreads();
    }

    #pragma unroll
    for (int mt = 0; mt < 4; mt++) {
        int r0 = m0 + warpM * 64 + mt * 16 + gid;
        #pragma unroll
        for (int nt = 0; nt < 4; nt++) {
            int cc = n0 + warpN * 32 + nt * 8 + 2 * tig;
            float2 v0 = make_float2(c[mt][nt][0], c[mt][nt][1]);
            float2 v1 = make_float2(c[mt][nt][2], c[mt][nt][3]);
            size_t o0 = (size_t)r0 * N + cc;
            size_t o1 = (size_t)(r0 + 8) * N + cc;
            if (res) {
                float2 q0 = *(const float2*)(res + o0);
                float2 q1 = *(const float2*)(res + o1);
                v0.x += q0.x; v0.y += q0.y;
                v1.x += q1.x; v1.y += q1.y;
            }
            *(float2*)(C + o0) = v0;
            *(float2*)(C + o1) = v1;
        }
    }
}

// ---------------- naive RoPE — REVERTED to PASSING R14 double-trig version ----
__global__ __launch_bounds__(256) void nrope_kernel(float* __restrict__ qkv) {
    int idx = blockIdx.x * 256 + threadIdx.x;
    if (idx >= ROWS * HEADS * 32) return;
    int p = idx & 31;
    int h = (idx >> 5) % HEADS;
    int row = idx / (32 * HEADS);
    int s = row % SEQ;
    double invf = exp(-(double)p * (9.210340371976184 / 32.0));
    double fr = (double)s * invf;
    float c = (float)cos(fr), sn = (float)sin(fr);
    float* qp = qkv + (size_t)row * (3 * DMODEL) + h * HDIM;
    float a = qp[p], b = qp[p + 32];
    qp[p]      = a * c - b * sn;
    qp[p + 32] = b * c + a * sn;
    float* kp = qp + DMODEL;
    a = kp[p]; b = kp[p + 32];
    kp[p]      = a * c - b * sn;
    kp[p + 32] = b * c + a * sn;
}

// ---------------- flash-style windowed attention — UNCHANGED (passing R14) ----
__global__ __launch_bounds__(256) void fattn_kernel(const float* __restrict__ qkv,
                                                    const float* __restrict__ amask,
                                                    float* __restrict__ ctx) {
    __shared__ __nv_bfloat162 Ks[160][33];
    __shared__ __nv_bfloat162 Vs[160][33];
    __shared__ float Qw[8][64];

    int q0 = blockIdx.x * 32;
    int bh = blockIdx.y;
    int b = bh / HEADS, h = bh % HEADS;
    int t = threadIdx.x, w = t >> 5, lane = t & 31;
    const float* base  = qkv + (size_t)(b * SEQ) * (3*DMODEL) + h * HDIM;
    const float* kbase = base + DMODEL;
    const float* vbase = base + 2*DMODEL;

    for (int i = t; i < 160 * 32; i += 256) {
        int row = i >> 5, pr = i & 31;
        int kg = q0 - 64 + row;
        if (kg >= 0 && kg < SEQ) {
            size_t off = (size_t)kg * (3*DMODEL) + 2*pr;
            float2 kv = *(const float2*)(kbase + off);
            Ks[row][pr] = __floats2bfloat162_rn(kv.x, kv.y);
            float2 vv = *(const float2*)(vbase + off);
            Vs[row][pr] = __floats2bfloat162_rn(vv.x, vv.y);
        }
    }
    __syncthreads();

    for (int r = 0; r < 4; r++) {
        int qi = w * 4 + r;
        int q  = q0 + qi;
        const float* qrow = base + (size_t)q * (3*DMODEL);
        Qw[w][lane]      = qrow[lane];
        Qw[w][lane + 32] = qrow[lane + 32];
        __syncwarp();

        int lo = q - 64; if (lo < 0) lo = 0;
        int hi = q + 64; if (hi > SEQ - 1) hi = SEQ - 1;
        const float* mrow = amask + (size_t)(b * SEQ + q) * SEQ;

        float pc[5];
        float m = -1e30f;
        #pragma unroll
        for (int c = 0; c < 5; c++) {
            int j = lo + lane + 32*c;
            float sc = -1e30f;
            if (j <= hi) {
                int jl = j - (q0 - 64);
                float acc = 0.f;
                #pragma unroll
                for (int dp = 0; dp < 32; dp++) {
                    __nv_bfloat162 kk = Ks[jl][dp];
                    acc += Qw[w][2*dp]   * __bfloat162float(kk.x)
                         + Qw[w][2*dp+1] * __bfloat162float(kk.y);
                }
                sc = acc * 0.125f + mrow[j];
            }
            pc[c] = sc;
            m = fmaxf(m, sc);
        }
        #pragma unroll
        for (int o = 16; o; o >>= 1) m = fmaxf(m, __shfl_xor_sync(0xffffffffu, m, o));

        float s = 0.f;
        #pragma unroll
        for (int c = 0; c < 5; c++) {
            pc[c] = expf(pc[c] - m);
            s += pc[c];
        }
        #pragma unroll
        for (int o = 16; o; o >>= 1) s += __shfl_xor_sync(0xffffffffu, s, o);
        float inv = 1.f / s;

        float a0 = 0.f, a1 = 0.f;
        #pragma unroll
        for (int c = 0; c < 5; c++) {
            int jbase = lo + 32*c;
            if (jbase > hi) break;
            int jmax = hi - jbase; if (jmax > 31) jmax = 31;
            int jl0 = jbase - (q0 - 64);
            for (int jj = 0; jj <= jmax; jj++) {
                float p = __shfl_sync(0xffffffffu, pc[c], jj);
                __nv_bfloat162 v = Vs[jl0 + jj][lane];
                a0 += p * __bfloat162float(v.x);
                a1 += p * __bfloat162float(v.y);
            }
        }
        float* o = ctx + (size_t)(b * SEQ + q) * DMODEL + h * HDIM + 2*lane;
        o[0] = a0 * inv;
        o[1] = a1 * inv;
        __syncwarp();
    }
}

// ---------------- naive GLU — UNCHANGED (passing R14) --------------------------
__global__ __launch_bounds__(256) void nglu_kernel(const float* __restrict__ wiout,
                                                   float* __restrict__ glu) {
    size_t idx = (size_t)blockIdx.x * 256 + threadIdx.x;
    if (idx >= (size_t)ROWS * INTER) return;
    size_t row = idx / INTER;
    int col = (int)(idx % INTER);
    float x    = wiout[row * (2 * INTER) + col];
    float gate = wiout[row * (2 * INTER) + col + INTER];
    float ge = 0.5f * x * (1.f + erff(x * 0.70710678118654752f));
    glu[idx] = ge * gate;
}

// ------------------------------------------------------------------------------
extern "C" void kernel_launch(void* const* d_in, const int* in_sizes, int n_in,
                              void* d_out, int out_size) {
    const float* hidden  = (const float*)d_in[0];
    const float* amask   = (const float*)d_in[1];
    const float* g1      = (const float*)d_in[2];
    const float* wqkv    = (const float*)d_in[3];
    const float* wo_attn = (const float*)d_in[4];
    const float* g2      = (const float*)d_in[5];
    const float* wi      = (const float*)d_in[6];
    const float* wo_mlp  = (const float*)d_in[7];
    float* out = (float*)d_out;

    float *xn, *qkv, *ctx, *h, *wiout, *glu;
    cudaGetSymbolAddress((void**)&xn,    g_xn);
    cudaGetSymbolAddress((void**)&qkv,   g_qkv);
    cudaGetSymbolAddress((void**)&ctx,   g_ctx);
    cudaGetSymbolAddress((void**)&h,     g_h);
    cudaGetSymbolAddress((void**)&wiout, g_wiout);
    cudaGetSymbolAddress((void**)&glu,   g_glu);

    // 1. pre-attn LN
    nln_kernel<<<ROWS, 256>>>(hidden, g1, xn);
    // 2. QKV projection: [8192,768] @ [768,2304]  (tf32 tensor cores)
    tgemm_kernel<<<dim3((3*DMODEL)/TBN, ROWS/TBM), 256>>>(xn, wqkv, nullptr, qkv,
                                                          ROWS, 3*DMODEL, DMODEL);
    // 3. RoPE (R14 double-trig version)
    nrope_kernel<<<(ROWS*HEADS*32)/256, 256>>>(qkv);
    // 4. windowed attention (static-smem flash-style)
    fattn_kernel<<<dim3(SEQ/32, BATCH*HEADS), 256>>>(qkv, amask, ctx);
    // 5. output projection + residual
    tgemm_kernel<<<dim3(DMODEL/TBN, ROWS/TBM), 256>>>(ctx, wo_attn, hidden, h,
                                                      ROWS, DMODEL, DMODEL);
    // 6. pre-MLP LN
    nln_kernel<<<ROWS, 256>>>(h, g2, xn);
    // 7. Wi projection
    tgemm_kernel<<<dim3((2*INTER)/TBN, ROWS/TBM), 256>>>(xn, wi, nullptr, wiout,
                                                         ROWS, 2*INTER, DMODEL);
    // 8. GLU
    nglu_kernel<<<((size_t)ROWS*INTER + 255)/256, 256>>>(wiout, glu);
    // 9. Wo projection + residual
    tgemm_kernel<<<dim3(DMODEL/TBN, ROWS/TBM), 256>>>(glu, wo_mlp, h, out,
                                                      ROWS, DMODEL, INTER);
}